// round 3
// baseline (speedup 1.0000x reference)
#include <cuda_runtime.h>
#include <math.h>

#define BB 16
#define TT 4096
#define CC 8
#define FF 64
#define KW 11
#define LL 4096
#define TSEG 8

// Scratch (device globals; no runtime allocation). 16B-aligned: accessed as float4.
__device__ __align__(16) float g_A[BB * FF * TT];        // 16 MB: conv+BN -> softmax+posenc, [B][F][T]
__device__ __align__(16) float g_part[TSEG * BB * LL];   // 2 MB: partial T-sums of sigmoid(dense)

// ---------------- f32x2 packed helpers (sm_103a FFMA2) ----------------
__device__ __forceinline__ unsigned long long packff(float lo, float hi) {
    unsigned long long r;
    asm("mov.b64 %0, {%1, %2};" : "=l"(r) : "f"(lo), "f"(hi));
    return r;
}
__device__ __forceinline__ void unpackff(unsigned long long v, float& lo, float& hi) {
    asm("mov.b64 {%0, %1}, %2;" : "=f"(lo), "=f"(hi) : "l"(v));
}
__device__ __forceinline__ void ffma2(unsigned long long& d, unsigned long long a, unsigned long long b) {
    asm("fma.rn.f32x2 %0, %1, %2, %0;" : "+l"(d) : "l"(a), "l"(b));
}

// ---------------- Kernel 1: Conv1D (SAME) + BatchNorm -> g_A[b][f][t] ----------------
__global__ __launch_bounds__(256) void conv_bn_kernel(
    const float* __restrict__ x,        // [B,T,C]
    const float* __restrict__ conv_w,   // [K,C,F]
    const float* __restrict__ conv_b,   // [F]
    const float* __restrict__ gamma,
    const float* __restrict__ beta,
    const float* __restrict__ mean,
    const float* __restrict__ var)
{
    __shared__ __align__(16) float ws[KW * CC * FF];     // 5632 floats (float4-copied) — FIRST
    __shared__ __align__(16) float xs[266][9];           // halo tile, padded pitch

    const int tid = threadIdx.x;
    const int b  = blockIdx.y;
    const int t0 = blockIdx.x * 256;

    // load conv weights (contiguous)
    for (int i = tid; i < (KW * CC * FF) / 4; i += 256)
        ((float4*)ws)[i] = ((const float4*)conv_w)[i];

    // load x with halo of 5 on each side, zero padding
    for (int i = tid; i < 266; i += 256) {
        int t = t0 + i - 5;
        if (t >= 0 && t < TT) {
            const float* xp = x + ((size_t)b * TT + t) * CC;
            #pragma unroll
            for (int c = 0; c < CC; c++) xs[i][c] = xp[c];
        } else {
            #pragma unroll
            for (int c = 0; c < CC; c++) xs[i][c] = 0.f;
        }
    }
    __syncthreads();

    const int t = t0 + tid;
    for (int fo = 0; fo < FF; fo += 8) {
        float acc[8];
        #pragma unroll
        for (int j = 0; j < 8; j++) acc[j] = conv_b[fo + j];
        #pragma unroll
        for (int k = 0; k < KW; k++) {
            #pragma unroll
            for (int c = 0; c < CC; c++) {
                float xv = xs[tid + k][c];
                const float* wp = &ws[(k * CC + c) * FF + fo];
                #pragma unroll
                for (int j = 0; j < 8; j++) acc[j] = fmaf(xv, wp[j], acc[j]);
            }
        }
        #pragma unroll
        for (int j = 0; j < 8; j++) {
            int f = fo + j;
            float inv = rsqrtf(var[f] + 1e-3f);
            float val = (acc[j] - mean[f]) * inv * gamma[f] + beta[f];
            g_A[((size_t)b * FF + f) * TT + t] = val;
        }
    }
}

// ---------------- Kernel 2: softmax over T (per b,f) + sine positional encoding ----------------
__global__ __launch_bounds__(256) void softmax_pe_kernel()
{
    const int bf = blockIdx.x;           // b*64 + f
    const int f  = bf & (FF - 1);
    float* row = g_A + (size_t)bf * TT;
    const int tid = threadIdx.x;

    float v[16];
    #pragma unroll
    for (int i = 0; i < 16; i++) v[i] = row[tid + i * 256];

    float m = v[0];
    #pragma unroll
    for (int i = 1; i < 16; i++) m = fmaxf(m, v[i]);

    __shared__ float sred[8];
    #pragma unroll
    for (int o = 16; o > 0; o >>= 1) m = fmaxf(m, __shfl_xor_sync(0xffffffffu, m, o));
    if ((tid & 31) == 0) sred[tid >> 5] = m;
    __syncthreads();
    m = sred[0];
    #pragma unroll
    for (int w = 1; w < 8; w++) m = fmaxf(m, sred[w]);

    float s = 0.f;
    #pragma unroll
    for (int i = 0; i < 16; i++) { v[i] = __expf(v[i] - m); s += v[i]; }
    #pragma unroll
    for (int o = 16; o > 0; o >>= 1) s += __shfl_xor_sync(0xffffffffu, s, o);
    __syncthreads();
    if ((tid & 31) == 0) sred[tid >> 5] = s;
    __syncthreads();
    s = 0.f;
    #pragma unroll
    for (int w = 0; w < 8; w++) s += sred[w];

    float inv = __fdividef(1.f, s);

    // sine positional encoding: timescale = 1e-4 ** ((f & ~1)/64), even f -> sin, odd -> cos
    float ts = (float)pow(1.0e-4, (double)(f & ~1) / 64.0);
    bool odd = (f & 1) != 0;
    #pragma unroll
    for (int i = 0; i < 16; i++) {
        int t = tid + i * 256;
        float ang = (float)t * ts;
        float pe = odd ? cosf(ang) : sinf(ang);
        row[t] = v[i] * inv + pe;
    }
}

// ---------------- Kernel 3: fused dense GEMM (fp32 via FFMA2) + sigmoid + partial T-sum ----------------
// Tiles: 128 t x 64 l, K=64. Threads 256 = (tx:8 l-groups of 8) x (ty:32 t-groups of 4).
// Each block handles one (b, l-tile, t-segment of 512) -> 4 chunks of 128 t.
__global__ __launch_bounds__(256, 2) void gemm_sig_reduce_kernel(
    const float* __restrict__ W,     // [F, L] = [64, 4096]
    const float* __restrict__ bias)  // [L]
{
    __shared__ __align__(16) float Asm[64][128];   // 32 KB
    __shared__ __align__(16) float Wsm[64][64];    // 16 KB

    const int tid = threadIdx.x;
    const int tx = tid & 7;          // l-group
    const int ty = tid >> 3;         // t-group (0..31)
    const int bid = blockIdx.x;
    const int lt  = bid & 63;
    const int b   = (bid >> 6) & 15;
    const int seg = bid >> 10;       // 0..7
    const int l0  = lt * 64;

    // load W tile once (64x64)
    {
        int r0 = tid >> 4;           // 0..15
        int c4 = tid & 15;           // 0..15
        #pragma unroll
        for (int r = 0; r < 4; r++) {
            int fr = r * 16 + r0;
            *(float4*)&Wsm[fr][c4 * 4] = *(const float4*)&W[(size_t)fr * LL + l0 + c4 * 4];
        }
    }

    unsigned long long bp[4];
    #pragma unroll
    for (int p = 0; p < 4; p++)
        bp[p] = packff(bias[l0 + tx * 8 + 2 * p], bias[l0 + tx * 8 + 2 * p + 1]);

    float colsum[8];
    #pragma unroll
    for (int i = 0; i < 8; i++) colsum[i] = 0.f;

    const float* Ab = g_A + (size_t)b * FF * TT;

    for (int ch = 0; ch < 4; ch++) {
        const int t0 = seg * 512 + ch * 128;
        __syncthreads();   // previous chunk's smem reads done (and Wsm visible on ch=0)
        {
            int r0 = tid >> 5;       // 0..7
            int c4 = tid & 31;       // 0..31
            #pragma unroll
            for (int r = 0; r < 8; r++) {
                int fr = r * 8 + r0;
                *(float4*)&Asm[fr][c4 * 4] = *(const float4*)&Ab[(size_t)fr * TT + t0 + c4 * 4];
            }
        }
        __syncthreads();

        unsigned long long acc[4][4];
        #pragma unroll
        for (int j = 0; j < 4; j++)
            #pragma unroll
            for (int p = 0; p < 4; p++) acc[j][p] = bp[p];

        #pragma unroll 16
        for (int k = 0; k < 64; k++) {
            float4 av = *(const float4*)&Asm[k][ty * 4];
            ulonglong2 w01 = *(const ulonglong2*)&Wsm[k][tx * 8];
            ulonglong2 w23 = *(const ulonglong2*)&Wsm[k][tx * 8 + 4];
            unsigned long long a0 = packff(av.x, av.x);
            unsigned long long a1 = packff(av.y, av.y);
            unsigned long long a2 = packff(av.z, av.z);
            unsigned long long a3 = packff(av.w, av.w);
            ffma2(acc[0][0], a0, w01.x); ffma2(acc[0][1], a0, w01.y);
            ffma2(acc[0][2], a0, w23.x); ffma2(acc[0][3], a0, w23.y);
            ffma2(acc[1][0], a1, w01.x); ffma2(acc[1][1], a1, w01.y);
            ffma2(acc[1][2], a1, w23.x); ffma2(acc[1][3], a1, w23.y);
            ffma2(acc[2][0], a2, w01.x); ffma2(acc[2][1], a2, w01.y);
            ffma2(acc[2][2], a2, w23.x); ffma2(acc[2][3], a2, w23.y);
            ffma2(acc[3][0], a3, w01.x); ffma2(acc[3][1], a3, w01.y);
            ffma2(acc[3][2], a3, w23.x); ffma2(acc[3][3], a3, w23.y);
        }

        // sigmoid(y)*2-1 = (1-e^-y)/(1+e^-y), accumulate over the 4 t-rows
        #pragma unroll
        for (int j = 0; j < 4; j++) {
            #pragma unroll
            for (int p = 0; p < 4; p++) {
                float ylo, yhi;
                unpackff(acc[j][p], ylo, yhi);
                float el = __expf(-ylo);
                float eh = __expf(-yhi);
                colsum[2 * p]     += __fdividef(1.f - el, 1.f + el);
                colsum[2 * p + 1] += __fdividef(1.f - eh, 1.f + eh);
            }
        }
    }

    // block reduction over the 32 ty rows (deterministic, no atomics)
    __syncthreads();
    float* red = &Asm[0][0];          // reuse: 32 x 64 floats
    #pragma unroll
    for (int i = 0; i < 8; i++) red[ty * 64 + tx * 8 + i] = colsum[i];
    __syncthreads();
    #pragma unroll
    for (int s2 = 16; s2 > 0; s2 >>= 1) {
        if (ty < s2) {
            #pragma unroll
            for (int i = 0; i < 8; i++)
                red[ty * 64 + tx * 8 + i] += red[(ty + s2) * 64 + tx * 8 + i];
        }
        __syncthreads();
    }
    if (ty == 0) {
        #pragma unroll
        for (int i = 0; i < 8; i++)
            g_part[((size_t)seg * BB + b) * LL + l0 + tx * 8 + i] = red[tx * 8 + i];
    }
}

// ---------------- Kernel 4: Gaussian shifting layer (banded) ----------------
__global__ __launch_bounds__(256) void warp_out_kernel(
    const float* __restrict__ x,     // [B,T,C]
    float* __restrict__ out)         // [B,L,C]
{
    const int idx = blockIdx.x * 256 + threadIdx.x;   // b*L + l
    const int b = idx >> 12;
    const int l = idx & (LL - 1);

    float sh = 0.f;
    #pragma unroll
    for (int s = 0; s < TSEG; s++) sh += g_part[(size_t)s * BB * LL + idx];

    const float scale = (float)TT / (float)LL;        // = 1.0f
    const float center = ((float)(l + 1) + sh) * scale;

    int tlo = (int)ceilf(center - 7.f);
    int thi = (int)floorf(center + 7.f);
    if (tlo < 1)  tlo = 1;
    if (thi > TT) thi = TT;

    float acc[8] = {0.f, 0.f, 0.f, 0.f, 0.f, 0.f, 0.f, 0.f};
    const float* xb = x + (size_t)b * TT * CC;
    for (int t = tlo; t <= thi; t++) {
        float d = (float)t - center;
        float w = __expf(-d * d);                     // WIDTH = 1
        const float4* xp = (const float4*)(xb + (size_t)(t - 1) * CC);
        float4 x0 = xp[0];
        float4 x1 = xp[1];
        acc[0] = fmaf(w, x0.x, acc[0]);
        acc[1] = fmaf(w, x0.y, acc[1]);
        acc[2] = fmaf(w, x0.z, acc[2]);
        acc[3] = fmaf(w, x0.w, acc[3]);
        acc[4] = fmaf(w, x1.x, acc[4]);
        acc[5] = fmaf(w, x1.y, acc[5]);
        acc[6] = fmaf(w, x1.z, acc[6]);
        acc[7] = fmaf(w, x1.w, acc[7]);
    }

    const float inv = (float)(1.0 / 1.772637204826652);   // 1/AMPLITUDE
    float4* op = (float4*)(out + (size_t)idx * CC);
    op[0] = make_float4(acc[0] * inv, acc[1] * inv, acc[2] * inv, acc[3] * inv);
    op[1] = make_float4(acc[4] * inv, acc[5] * inv, acc[6] * inv, acc[7] * inv);
}

// ---------------- launch ----------------
extern "C" void kernel_launch(void* const* d_in, const int* in_sizes, int n_in,
                              void* d_out, int out_size)
{
    const float* x       = (const float*)d_in[0];
    const float* conv_w  = (const float*)d_in[1];
    const float* conv_b  = (const float*)d_in[2];
    const float* gamma   = (const float*)d_in[3];
    const float* beta    = (const float*)d_in[4];
    const float* mean    = (const float*)d_in[5];
    const float* var     = (const float*)d_in[6];
    const float* dense_w = (const float*)d_in[7];
    const float* dense_b = (const float*)d_in[8];
    float* out = (float*)d_out;

    conv_bn_kernel<<<dim3(TT / 256, BB), 256>>>(x, conv_w, conv_b, gamma, beta, mean, var);
    softmax_pe_kernel<<<BB * FF, 256>>>();
    gemm_sig_reduce_kernel<<<(LL / 64) * BB * TSEG, 256>>>(dense_w, dense_b);
    warp_out_kernel<<<(BB * LL) / 256, 256>>>(x, out);
}